// round 11
// baseline (speedup 1.0000x reference)
#include <cuda_runtime.h>
#include <cuda_bf16.h>
#include <math.h>
#include <stdint.h>

#define BATCH 32
#define TLEN  4096
#define HCH   256
#define NPOS  (BATCH*TLEN)      // 131072
#define LLAYER 4
#define OUTCH 58
#define OPAD  64

// ---------------- scratch ----------------
// g_y: chunk-tiled swizzled: [nblk][chunk(8)][row(64)][32 floats], 16B unit u stored at u^(row&7)
// g_wt: [layer][chunk(8)][row(256)][32 floats], same swizzle
__device__ float g_h [NPOS*HCH];
__device__ float g_y [NPOS*HCH];
__device__ float g_wt[LLAYER*HCH*HCH];
__device__ float g_p[NPOS*OPAD];
__device__ float g_pw[OPAD*HCH];
__device__ float g_pb[OPAD];
__device__ float g_lad[BATCH*2*TLEN];

// ---------------- helpers ----------------
__device__ __forceinline__ uint32_t smem_u32(const void* p){
  uint32_t a;
  asm("{ .reg .u64 t; cvta.to.shared.u64 t, %1; cvt.u32.u64 %0, t; }" : "=r"(a) : "l"(p));
  return a;
}
__device__ __forceinline__ void ldsm4(unsigned &r0, unsigned &r1, unsigned &r2, unsigned &r3, uint32_t a){
  asm volatile("ldmatrix.sync.aligned.m8n8.x4.shared.b16 {%0,%1,%2,%3}, [%4];"
    : "=r"(r0),"=r"(r1),"=r"(r2),"=r"(r3) : "r"(a));
}
__device__ __forceinline__ void mma_tf32(float* d, const unsigned* a, unsigned b0, unsigned b1){
  asm volatile("mma.sync.aligned.m16n8k8.row.col.f32.tf32.tf32.f32 "
    "{%0,%1,%2,%3}, {%4,%5,%6,%7}, {%8,%9}, {%0,%1,%2,%3};"
    : "+f"(d[0]),"+f"(d[1]),"+f"(d[2]),"+f"(d[3])
    : "r"(a[0]),"r"(a[1]),"r"(a[2]),"r"(a[3]),"r"(b0),"r"(b1));
}
__device__ __forceinline__ float tf32_rna(float x){
  uint32_t r;
  asm("cvt.rna.tf32.f32 %0, %1;" : "=r"(r) : "f"(x));
  return __uint_as_float(r);
}
__device__ __forceinline__ float gelu_exact(float x){
  return 0.5f*x*(1.f+erff(x*0.70710678118654752f));
}
__device__ __forceinline__ float softplusf(float x){
  return (x > 20.f) ? x : log1pf(expf(x));
}

#define MBAR_INIT(mb, c)  asm volatile("mbarrier.init.shared.b64 [%0], %1;" :: "r"(mb), "r"((uint32_t)(c)) : "memory")
#define MBAR_EXPECT_TX(mb, tx) asm volatile("mbarrier.arrive.expect_tx.shared.b64 _, [%0], %1;" :: "r"(mb), "r"((uint32_t)(tx)) : "memory")
#define MBAR_WAIT(mb, par) do {                                                   \
  uint32_t _m = (mb); uint32_t _p = (par); uint32_t _d;                           \
  asm volatile("{\n\t.reg .pred p;\n\t"                                           \
    "mbarrier.try_wait.parity.acquire.cta.shared::cta.b64 p, [%1], %2;\n\t"       \
    "selp.b32 %0, 1, 0, p;\n\t}" : "=r"(_d) : "r"(_m), "r"(_p) : "memory");       \
  if (!_d) {                                                                      \
    asm volatile("{\n\t.reg .pred P1;\n\t"                                        \
      "W_%=:\n\t"                                                                 \
      "mbarrier.try_wait.parity.acquire.cta.shared::cta.b64 P1, [%0], %1, 0x989680;\n\t" \
      "@P1 bra.uni D_%=;\n\t"                                                     \
      "bra.uni W_%=;\n\t"                                                         \
      "D_%=:\n\t}" :: "r"(_m), "r"(_p) : "memory");                               \
  }                                                                               \
} while(0)

__device__ __forceinline__ void bulk_g2s(uint32_t dst, const void* src, uint32_t bytes, uint32_t mbar){
  asm volatile("cp.async.bulk.shared::cluster.global.mbarrier::complete_tx::bytes [%0], [%1], %2, [%3];"
    :: "r"(dst), "l"(src), "r"(bytes), "r"(mbar) : "memory");
}

// ---------------- weight prep: tf32 round + chunk-tiled swizzled layout ----------------
__global__ void k_wprep(const float* __restrict__ w){
  int i = blockIdx.x*256 + threadIdx.x;
  int layer = i >> 14;
  int j = i & 16383;
  int o = j >> 6;
  int cu = j & 63;
  int chunk = cu >> 3, uu = cu & 7;
  const float* src = w + (size_t)layer*65536 + o*256 + cu*4;
  float4 v = *(const float4*)src;
  v.x = tf32_rna(v.x); v.y = tf32_rna(v.y); v.z = tf32_rna(v.z); v.w = tf32_rna(v.w);
  float* dst = g_wt + (size_t)layer*65536 + chunk*8192 + o*32 + ((uu ^ (o & 7)) << 2);
  *(float4*)dst = v;
}

// store 8 channels (c = lid*8) of position n into swizzled g_y
__device__ __forceinline__ void store_y(int n, int c, const float* o_){
  int nblk = n >> 6, row = n & 63;
  int cu0 = c >> 2;
  int chunk = cu0 >> 3, uu = cu0 & 7;
  float* base = g_y + (size_t)nblk*16384 + chunk*2048 + row*32;
  int r7 = row & 7;
  *(float4*)(base + ((uu ^ r7) << 2))       = *(const float4*)&o_[0];
  *(float4*)(base + (((uu+1) ^ r7) << 2))   = *(const float4*)&o_[4];
}

// ======= layer 1-3 dwln: 4 positions per warp, vectorized param loads =======
__global__ void __launch_bounds__(256) k_dwln(const float* __restrict__ mask,
                       const float* __restrict__ sw, const float* __restrict__ sb,
                       const float* __restrict__ gm, const float* __restrict__ bt, int dil){
  int w = threadIdx.x >> 5, lid = threadIdx.x & 31;
  int n0 = blockIdx.x*32 + w*4;
  int c = lid*8;

  float s3[24], sbv[8], gmv[8], btv[8];
  #pragma unroll
  for (int q=0;q<6;q++) *(float4*)&s3[q*4] = *(const float4*)&sw[c*3 + q*4];
  *(float4*)&sbv[0] = *(const float4*)&sb[c]; *(float4*)&sbv[4] = *(const float4*)&sb[c+4];
  *(float4*)&gmv[0] = *(const float4*)&gm[c]; *(float4*)&gmv[4] = *(const float4*)&gm[c+4];
  *(float4*)&btv[0] = *(const float4*)&bt[c]; *(float4*)&btv[4] = *(const float4*)&bt[c+4];

  float v[4][8];
  #pragma unroll
  for (int p=0;p<4;p++){
    int n = n0 + p;
    int t = n & (TLEN-1);
    float m0 = mask[n];
    float hc[8];
    *(float4*)&hc[0] = *(const float4*)&g_h[(size_t)n*HCH + c];
    *(float4*)&hc[4] = *(const float4*)&g_h[(size_t)n*HCH + c + 4];
    #pragma unroll
    for (int j=0;j<8;j++) v[p][j] = sbv[j] + s3[j*3+1]*hc[j]*m0;
    if (t >= dil){
      float mm = mask[n-dil];
      float hl[8];
      *(float4*)&hl[0] = *(const float4*)&g_h[(size_t)(n-dil)*HCH + c];
      *(float4*)&hl[4] = *(const float4*)&g_h[(size_t)(n-dil)*HCH + c + 4];
      #pragma unroll
      for (int j=0;j<8;j++) v[p][j] += s3[j*3+0]*hl[j]*mm;
    }
    if (t + dil < TLEN){
      float mm = mask[n+dil];
      float hr[8];
      *(float4*)&hr[0] = *(const float4*)&g_h[(size_t)(n+dil)*HCH + c];
      *(float4*)&hr[4] = *(const float4*)&g_h[(size_t)(n+dil)*HCH + c + 4];
      #pragma unroll
      for (int j=0;j<8;j++) v[p][j] += s3[j*3+2]*hr[j]*mm;
    }
  }

  #pragma unroll
  for (int p=0;p<4;p++){
    int n = n0 + p;
    float ls = 0.f;
    #pragma unroll
    for (int j=0;j<8;j++) ls += v[p][j];
    #pragma unroll
    for (int o=16;o;o>>=1) ls += __shfl_xor_sync(0xffffffffu, ls, o);
    float mean = ls * (1.f/HCH);
    float sq = 0.f;
    #pragma unroll
    for (int j=0;j<8;j++){ v[p][j] -= mean; sq += v[p][j]*v[p][j]; }
    #pragma unroll
    for (int o=16;o;o>>=1) sq += __shfl_xor_sync(0xffffffffu, sq, o);
    float rstd = rsqrtf(sq * (1.f/HCH) + 1e-5f);

    float o_[8];
    #pragma unroll
    for (int j=0;j<8;j++){
      float yn = v[p][j]*rstd*gmv[j] + btv[j];
      o_[j] = tf32_rna(gelu_exact(yn));
    }
    store_y(n, c, o_);
  }
}

// ======= layer-0 fused: pre-1x1 on the fly + dwconv(dil=1) + LN + GELU =======
__global__ void __launch_bounds__(256) k_dwln_pre(const float* __restrict__ x,
                           const float* __restrict__ mask,
                           const float* __restrict__ pw, const float* __restrict__ pb,
                           const float* __restrict__ sw, const float* __restrict__ sb,
                           const float* __restrict__ gm, const float* __restrict__ bt){
  int w = threadIdx.x >> 5, lid = threadIdx.x & 31;
  int n0 = blockIdx.x*32 + w*4;
  int t0 = n0 & (TLEN-1);
  int b = n0 >> 12;
  int c = lid*8;

  float pwv[16], pbv[8], s3[24], sbv[8], gmv[8], btv[8];
  #pragma unroll
  for (int q=0;q<4;q++) *(float4*)&pwv[q*4] = *(const float4*)&pw[c*2 + q*4];
  *(float4*)&pbv[0] = *(const float4*)&pb[c]; *(float4*)&pbv[4] = *(const float4*)&pb[c+4];
  #pragma unroll
  for (int q=0;q<6;q++) *(float4*)&s3[q*4] = *(const float4*)&sw[c*3 + q*4];
  *(float4*)&sbv[0] = *(const float4*)&sb[c]; *(float4*)&sbv[4] = *(const float4*)&sb[c+4];
  *(float4*)&gmv[0] = *(const float4*)&gm[c]; *(float4*)&gmv[4] = *(const float4*)&gm[c+4];
  *(float4*)&btv[0] = *(const float4*)&bt[c]; *(float4*)&btv[4] = *(const float4*)&bt[c+4];

  float x0v[6], x1v[6], mv[6];
  #pragma unroll
  for (int i=0;i<6;i++){
    int ti = t0 - 1 + i;
    bool ok = (ti >= 0) && (ti < TLEN);
    int tc = ok ? ti : 0;
    x0v[i] = x[(b*4+0)*TLEN + tc];
    x1v[i] = x[(b*4+1)*TLEN + tc];
    mv[i]  = ok ? mask[b*TLEN + tc] : 0.f;
  }

  float v[4][8];
  #pragma unroll
  for (int p=0;p<4;p++){
    int n = n0 + p;
    int t = t0 + p;
    bool hasL = (t >= 1), hasR = (t + 1 < TLEN);
    float hc[8];
    #pragma unroll
    for (int j=0;j<8;j++){
      float wa = pwv[j*2], wb = pwv[j*2+1], pbc = pbv[j];
      float h0 = fmaf(wa, x0v[p+1], fmaf(wb, x1v[p+1], pbc));
      hc[j] = h0;
      float acc = sbv[j] + s3[j*3+1]*h0*mv[p+1];
      if (hasL){ float hl = fmaf(wa, x0v[p],   fmaf(wb, x1v[p],   pbc)); acc += s3[j*3+0]*hl*mv[p]; }
      if (hasR){ float hr = fmaf(wa, x0v[p+2], fmaf(wb, x1v[p+2], pbc)); acc += s3[j*3+2]*hr*mv[p+2]; }
      v[p][j] = acc;
    }
    *(float4*)&g_h[(size_t)n*HCH + c]     = *(float4*)&hc[0];
    *(float4*)&g_h[(size_t)n*HCH + c + 4] = *(float4*)&hc[4];
  }

  #pragma unroll
  for (int p=0;p<4;p++){
    int n = n0 + p;
    float ls = 0.f;
    #pragma unroll
    for (int j=0;j<8;j++) ls += v[p][j];
    #pragma unroll
    for (int o=16;o;o>>=1) ls += __shfl_xor_sync(0xffffffffu, ls, o);
    float mean = ls * (1.f/HCH);
    float sq = 0.f;
    #pragma unroll
    for (int j=0;j<8;j++){ v[p][j] -= mean; sq += v[p][j]*v[p][j]; }
    #pragma unroll
    for (int o=16;o;o>>=1) sq += __shfl_xor_sync(0xffffffffu, sq, o);
    float rstd = rsqrtf(sq * (1.f/HCH) + 1e-5f);

    float o_[8];
    #pragma unroll
    for (int j=0;j<8;j++){
      float yn = v[p][j]*rstd*gmv[j] + btv[j];
      o_[j] = tf32_rna(gelu_exact(yn));
    }
    store_y(n, c, o_);
  }
}

// ======== fused tf32 mma GEMM, bulk async, 512 threads / 16 warps (2M x 8N) ========
// CTA: 64 positions x 256 out-ch. Warp tile 32x32 (acc 32 regs) -> 2 CTAs/SM = 32 warps.
#define OFF_A   0                 // 2 stages * 8192
#define OFF_B   16384             // 2 stages * 32768
#define OFF_PAR 81920             // 3 * 1024
#define OFF_RED 84992             // 64 rows * 16 floats = 4096
#define OFF_MBR 89088             // 2 mbarriers * 16B
#define GSMEM   89152

__global__ void __launch_bounds__(512, 2) k_gemmfused(int layer,
                       const float* __restrict__ bias,
                       const float* __restrict__ gm, const float* __restrict__ bt){
  extern __shared__ char smem[];
  uint32_t sbase = smem_u32(smem);
  float* s_bias = (float*)(smem + OFF_PAR);
  float* s_g    = (float*)(smem + OFF_PAR + 1024);
  float* s_bt   = (float*)(smem + OFF_PAR + 2048);
  float* s_red  = (float*)(smem + OFF_RED);

  int tid = threadIdx.x, lane = tid & 31, wid = tid >> 5;
  int warpM = wid & 1, warpN = wid >> 1;     // 2 x 8
  int g = lane >> 2, tig = lane & 3;
  int mat = lane >> 3, mr = lane & 7;
  int n0 = blockIdx.x * 64;

  const char* gB = (const char*)(g_wt + (size_t)layer*65536);
  const char* gA = (const char*)(g_y  + (size_t)blockIdx.x*16384);

  if (tid < 256){ s_bias[tid] = bias[tid]; s_g[tid] = gm[tid]; s_bt[tid] = bt[tid]; }
  if (tid == 0){ MBAR_INIT(sbase + OFF_MBR, 1); MBAR_INIT(sbase + OFF_MBR + 16, 1); }
  __syncthreads();

  float acc[2][4][4];
  #pragma unroll
  for (int mf=0;mf<2;mf++)
    #pragma unroll
    for (int nf=0;nf<4;nf++)
      #pragma unroll
      for (int k=0;k<4;k++) acc[mf][nf][k]=0.f;

  int arow_l = (mat & 1)*8 + mr;   int amh = mat >> 1;
  int brow_l = (mat >> 1)*8 + mr;  int bmh = mat & 1;
  uint32_t aBase0 = sbase + OFF_A + (uint32_t)((warpM*32 + arow_l)*128);
  uint32_t bBase0 = sbase + OFF_B + (uint32_t)((warpN*32 + brow_l)*128);

  #define ISSUE(q) {                                                       \
    uint32_t _mb = sbase + OFF_MBR + ((q)&1)*16;                           \
    MBAR_EXPECT_TX(_mb, 40960);                                            \
    bulk_g2s(sbase + OFF_A + ((q)&1)*8192,  gA + (size_t)(q)*8192,  8192,  _mb); \
    bulk_g2s(sbase + OFF_B + ((q)&1)*32768, gB + (size_t)(q)*32768, 32768, _mb); \
  }

  if (tid == 0) ISSUE(0);

  for (int q = 0; q < 8; q++){
    if (tid == 0 && q + 1 < 8) ISSUE(q+1);
    MBAR_WAIT(sbase + OFF_MBR + (q&1)*16, (q>>1)&1);

    uint32_t aBase = aBase0 + (q&1)*8192;
    uint32_t bBase = bBase0 + (q&1)*32768;

    #pragma unroll
    for (int ks=0; ks<4; ks++){
      uint32_t swa = (uint32_t)(((2*ks + amh) ^ mr) << 4);
      uint32_t swb = (uint32_t)(((2*ks + bmh) ^ mr) << 4);
      unsigned afr[2][4];
      ldsm4(afr[0][0], afr[0][1], afr[0][2], afr[0][3], aBase + swa);
      ldsm4(afr[1][0], afr[1][1], afr[1][2], afr[1][3], aBase + 2048 + swa);
      unsigned bfr[4][2];
      #pragma unroll
      for (int np=0; np<2; np++){
        unsigned t0,t1,t2,t3;
        ldsm4(t0,t1,t2,t3, bBase + np*2048 + swb);
        bfr[2*np][0]=t0; bfr[2*np][1]=t1; bfr[2*np+1][0]=t2; bfr[2*np+1][1]=t3;
      }
      #pragma unroll
      for (int nf=0; nf<4; nf++){
        mma_tf32(acc[0][nf], afr[0], bfr[nf][0], bfr[nf][1]);
        mma_tf32(acc[1][nf], afr[1], bfr[nf][0], bfr[nf][1]);
      }
    }
    __syncthreads();
  }

  // ---- epilogue: bias, row stats (8 warpN groups), LN, GELU, residual ----
  float s[4]  = {0.f,0.f,0.f,0.f};
  float sq[4] = {0.f,0.f,0.f,0.f};
  #pragma unroll
  for (int mf=0; mf<2; mf++)
    #pragma unroll
    for (int nf=0; nf<4; nf++){
      int ch0 = warpN*32 + nf*8 + tig*2;
      float b0 = s_bias[ch0], b1 = s_bias[ch0+1];
      acc[mf][nf][0]+=b0; acc[mf][nf][1]+=b1;
      acc[mf][nf][2]+=b0; acc[mf][nf][3]+=b1;
      s [mf*2+0] += acc[mf][nf][0]+acc[mf][nf][1];
      sq[mf*2+0] += acc[mf][nf][0]*acc[mf][nf][0] + acc[mf][nf][1]*acc[mf][nf][1];
      s [mf*2+1] += acc[mf][nf][2]+acc[mf][nf][3];
      sq[mf*2+1] += acc[mf][nf][2]*acc[mf][nf][2] + acc[mf][nf][3]*acc[mf][nf][3];
    }
  #pragma unroll
  for (int sl=0; sl<4; sl++){
    s [sl] += __shfl_xor_sync(0xffffffffu, s [sl], 1);
    s [sl] += __shfl_xor_sync(0xffffffffu, s [sl], 2);
    sq[sl] += __shfl_xor_sync(0xffffffffu, sq[sl], 1);
    sq[sl] += __shfl_xor_sync(0xffffffffu, sq[sl], 2);
  }
  __syncthreads();
  if (tig == 0){
    #pragma unroll
    for (int sl=0; sl<4; sl++){
      int mf = sl >> 1, h = sl & 1;
      int row = warpM*32 + mf*16 + h*8 + g;
      s_red[row*16 + warpN*2 + 0] = s[sl];
      s_red[row*16 + warpN*2 + 1] = sq[sl];
    }
  }
  __syncthreads();

  float mean_[4], rstd_[4];
  #pragma unroll
  for (int sl=0; sl<4; sl++){
    int mf = sl >> 1, h = sl & 1;
    int row = warpM*32 + mf*16 + h*8 + g;
    float su = 0.f, qq = 0.f;
    #pragma unroll
    for (int k=0; k<8; k++){ su += s_red[row*16 + 2*k]; qq += s_red[row*16 + 2*k + 1]; }
    float mn = su * (1.f/HCH);
    float var = qq * (1.f/HCH) - mn*mn;
    mean_[sl] = mn;
    rstd_[sl] = rsqrtf(var + 1e-5f);
  }

  #pragma unroll
  for (int mf=0; mf<2; mf++)
    #pragma unroll
    for (int nf=0; nf<4; nf++){
      int ch0 = warpN*32 + nf*8 + tig*2;
      float g0 = s_g[ch0], g1 = s_g[ch0+1];
      float t0 = s_bt[ch0], t1 = s_bt[ch0+1];
      #pragma unroll
      for (int h=0; h<2; h++){
        int sl = mf*2 + h;
        int row = n0 + warpM*32 + mf*16 + h*8 + g;
        float v0 = (acc[mf][nf][h*2+0] - mean_[sl])*rstd_[sl]*g0 + t0;
        float v1 = (acc[mf][nf][h*2+1] - mean_[sl])*rstd_[sl]*g1 + t1;
        float2* ptr = (float2*)&g_h[(size_t)row*HCH + ch0];
        float2 hv = *ptr;
        hv.x += gelu_exact(v0);
        hv.y += gelu_exact(v1);
        *ptr = hv;
      }
    }
}

// ---------------- pad proj weights ----------------
__global__ void k_padw(const float* __restrict__ pjw, const float* __restrict__ pjb){
  int o = blockIdx.x, c = threadIdx.x;
  g_pw[o*HCH + c] = (o < OUTCH) ? pjw[o*HCH + c] : 0.f;
  if (c == 0) g_pb[o] = (o < OUTCH) ? pjb[o] : 0.f;
}

// ---------------- projection GEMM (fp32 SIMT; precision-critical path) ----------------
__global__ void __launch_bounds__(256) k_projgemm(const float* __restrict__ mask){
  __shared__ float sA[16][128];
  __shared__ float sB[16][64];
  int tid = threadIdx.x;
  int n0 = blockIdx.x*128;
  int tx = tid & 7, ty = tid >> 3;
  float acc[4][8];
  #pragma unroll
  for (int i=0;i<4;i++)
    #pragma unroll
    for (int j=0;j<8;j++) acc[i][j]=0.f;

  for (int c0=0;c0<HCH;c0+=16){
    #pragma unroll
    for (int u=0;u<2;u++){
      int f = tid + u*256;
      int row = f >> 2;
      int cc4 = (f & 3) << 2;
      float m = mask[n0+row];
      float4 av = *(const float4*)&g_h[(size_t)(n0+row)*HCH + c0 + cc4];
      sA[cc4+0][row]=av.x*m; sA[cc4+1][row]=av.y*m; sA[cc4+2][row]=av.z*m; sA[cc4+3][row]=av.w*m;
    }
    {
      int row = tid >> 2;
      int cc4 = (tid & 3) << 2;
      float4 wv = *(const float4*)&g_pw[row*HCH + c0 + cc4];
      sB[cc4+0][row]=wv.x; sB[cc4+1][row]=wv.y; sB[cc4+2][row]=wv.z; sB[cc4+3][row]=wv.w;
    }
    __syncthreads();
    #pragma unroll
    for (int cc=0; cc<16; cc++){
      float a[4], b[8];
      *(float4*)&a[0] = *(const float4*)&sA[cc][ty*4];
      *(float4*)&b[0] = *(const float4*)&sB[cc][tx*8];
      *(float4*)&b[4] = *(const float4*)&sB[cc][tx*8+4];
      #pragma unroll
      for (int i=0;i<4;i++)
        #pragma unroll
        for (int j=0;j<8;j++) acc[i][j] = fmaf(a[i], b[j], acc[i][j]);
    }
    __syncthreads();
  }
  #pragma unroll
  for (int i=0;i<4;i++){
    int n = n0 + ty*4 + i;
    float m = mask[n];
    #pragma unroll
    for (int j=0;j<8;j++){
      int o = tx*8 + j;
      g_p[(size_t)n*OPAD + o] = (acc[i][j] + g_pb[o]) * m;
    }
  }
}

// ---------------- rational-quadratic spline ----------------
__global__ void k_spline(const float* __restrict__ x, const float* __restrict__ mask,
                         float* __restrict__ out){
  int i = blockIdx.x*256 + threadIdx.x;
  int t = i & (TLEN-1);
  int bc = i >> 12;
  int c = bc & 1, b = bc >> 1;
  float m = mask[b*TLEN + t];
  const float* p = &g_p[(size_t)(b*TLEN + t)*OPAD + c*29];
  float x1 = x[(b*4 + 2 + c)*TLEN + t];

  out[(b*4 + c)*TLEN + t] = x[(b*4 + c)*TLEN + t] * m;

  const float scale = 0.0625f;
  float ew[10], eh[10];
  float mw = -1e30f, mh = -1e30f;
  #pragma unroll
  for (int j=0;j<10;j++){ mw = fmaxf(mw, p[j]*scale); mh = fmaxf(mh, p[10+j]*scale); }
  float sw = 0.f, sh = 0.f;
  #pragma unroll
  for (int j=0;j<10;j++){
    ew[j] = expf(p[j]*scale - mw);    sw += ew[j];
    eh[j] = expf(p[10+j]*scale - mh); sh += eh[j];
  }
  float invsw = 1.f/sw, invsh = 1.f/sh;
  float xc = fminf(fmaxf(x1, -5.f), 5.f);

  float cumw = 0.f, cumh = 0.f;
  float cwj = -5.f, chj = -5.f;
  int idx = 9;
  float in_cw = 0.f, in_w = 1.f, in_ch = 0.f, in_h = 1.f;
  bool found = false;
  #pragma unroll
  for (int j=0;j<10;j++){
    cumw += 0.001f + 0.99f*ew[j]*invsw;
    cumh += 0.001f + 0.99f*eh[j]*invsh;
    float nw = (j==9) ? 5.f : fmaf(10.f, cumw, -5.f);
    float nh = (j==9) ? 5.f : fmaf(10.f, cumh, -5.f);
    if (!found && (xc < nw || j==9)){
      found = true; idx = j;
      in_cw = cwj; in_w = nw - cwj;
      in_ch = chj; in_h = nh - chj;
    }
    cwj = nw; chj = nh;
  }
  float dk  = (idx==0) ? 1.f : 0.001f + softplusf(p[20 + idx - 1]);
  float dk1 = (idx==9) ? 1.f : 0.001f + softplusf(p[20 + idx]);
  float delta = in_h / in_w;
  float th  = (xc - in_cw) / in_w;
  float th2 = th*th;
  float t1m = th*(1.f - th);
  float num = in_h * (delta*th2 + dk*t1m);
  float den = delta + (dk + dk1 - 2.f*delta)*t1m;
  float y = in_ch + num/den;
  float omt = 1.f - th;
  float dnum = delta*delta*(dk1*th2 + 2.f*delta*t1m + dk*omt*omt);
  float lad = logf(dnum) - 2.f*logf(den);

  bool inside = (x1 >= -5.f) && (x1 <= 5.f);
  y   = inside ? y   : x1;
  lad = inside ? lad : 0.f;

  out[(b*4 + 2 + c)*TLEN + t] = y * m;
  g_lad[i] = lad * m;
}

__global__ void k_reduce(float* __restrict__ out){
  int b = blockIdx.x;
  float s = 0.f;
  for (int j = threadIdx.x; j < 2*TLEN; j += 256) s += g_lad[b*2*TLEN + j];
  __shared__ float sm[8];
  #pragma unroll
  for (int o=16;o;o>>=1) s += __shfl_xor_sync(0xffffffffu, s, o);
  if ((threadIdx.x&31)==0) sm[threadIdx.x>>5]=s;
  __syncthreads();
  if (threadIdx.x == 0){
    float r = sm[0]+sm[1]+sm[2]+sm[3]+sm[4]+sm[5]+sm[6]+sm[7];
    out[BATCH*4*TLEN + b] = r;
  }
}

extern "C" void kernel_launch(void* const* d_in, const int* in_sizes, int n_in,
                              void* d_out, int out_size){
  const float* x     = (const float*)d_in[0];
  const float* xm    = (const float*)d_in[1];
  const float* pre_w = (const float*)d_in[2];
  const float* pre_b = (const float*)d_in[3];
  const float* sep_w = (const float*)d_in[4];
  const float* sep_b = (const float*)d_in[5];
  const float* c1w   = (const float*)d_in[6];
  const float* c1b   = (const float*)d_in[7];
  const float* n1g   = (const float*)d_in[8];
  const float* n1b   = (const float*)d_in[9];
  const float* n2g   = (const float*)d_in[10];
  const float* n2b   = (const float*)d_in[11];
  const float* pjw   = (const float*)d_in[12];
  const float* pjb   = (const float*)d_in[13];
  float* out = (float*)d_out;

  static int smem_set = 0;
  if (!smem_set){
    cudaFuncSetAttribute(k_gemmfused, cudaFuncAttributeMaxDynamicSharedMemorySize, GSMEM);
    smem_set = 1;
  }

  k_wprep<<<(LLAYER*HCH*HCH/4)/256, 256>>>(c1w);

  int dil = 1;
  for (int i=0;i<LLAYER;i++){
    if (i == 0)
      k_dwln_pre<<<NPOS/32, 256>>>(x, xm, pre_w, pre_b, sep_w, sep_b, n1g, n1b);
    else
      k_dwln<<<NPOS/32, 256>>>(xm, sep_w + i*HCH*3, sep_b + i*HCH,
                               n1g + i*HCH, n1b + i*HCH, dil);
    k_gemmfused<<<NPOS/64, 512, GSMEM>>>(i, c1b + i*HCH, n2g + i*HCH, n2b + i*HCH);
    dil *= 3;
  }

  k_padw<<<OPAD, HCH>>>(pjw, pjb);
  k_projgemm<<<NPOS/128, 256>>>(xm);
  k_spline<<<(BATCH*2*TLEN)/256, 256>>>(x, xm, out);
  k_reduce<<<BATCH, 256>>>(out);
}

// round 13
// speedup vs baseline: 1.1543x; 1.1543x over previous
#include <cuda_runtime.h>
#include <cuda_bf16.h>
#include <math.h>
#include <stdint.h>

#define BATCH 32
#define TLEN  4096
#define HCH   256
#define NPOS  (BATCH*TLEN)      // 131072
#define LLAYER 4
#define OUTCH 58
#define OPAD  64

// ---------------- scratch ----------------
// g_y: chunk-tiled swizzled: [nblk][chunk(8)][row(64)][32 floats], 16B unit u stored at u^(row&7)
// g_wt: [layer][chunk(8)][row(256)][32 floats], same swizzle
__device__ float g_h [NPOS*HCH];
__device__ float g_y [NPOS*HCH];
__device__ float g_wt[LLAYER*HCH*HCH];
__device__ float g_p[NPOS*OPAD];
__device__ __nv_bfloat16 g_pwh[4*OPAD*OPAD];  // [chunk(4)][row(64)][64 bf16] swizzled
__device__ __nv_bfloat16 g_pwl[4*OPAD*OPAD];
__device__ float g_pb[OPAD];
__device__ float g_lad[BATCH*2*TLEN];

// ---------------- helpers ----------------
__device__ __forceinline__ uint32_t smem_u32(const void* p){
  uint32_t a;
  asm("{ .reg .u64 t; cvta.to.shared.u64 t, %1; cvt.u32.u64 %0, t; }" : "=r"(a) : "l"(p));
  return a;
}
__device__ __forceinline__ void ldsm4(unsigned &r0, unsigned &r1, unsigned &r2, unsigned &r3, uint32_t a){
  asm volatile("ldmatrix.sync.aligned.m8n8.x4.shared.b16 {%0,%1,%2,%3}, [%4];"
    : "=r"(r0),"=r"(r1),"=r"(r2),"=r"(r3) : "r"(a));
}
__device__ __forceinline__ void mma_tf32(float* d, const unsigned* a, unsigned b0, unsigned b1){
  asm volatile("mma.sync.aligned.m16n8k8.row.col.f32.tf32.tf32.f32 "
    "{%0,%1,%2,%3}, {%4,%5,%6,%7}, {%8,%9}, {%0,%1,%2,%3};"
    : "+f"(d[0]),"+f"(d[1]),"+f"(d[2]),"+f"(d[3])
    : "r"(a[0]),"r"(a[1]),"r"(a[2]),"r"(a[3]),"r"(b0),"r"(b1));
}
__device__ __forceinline__ void mma_bf16(float* d, const unsigned* a, unsigned b0, unsigned b1){
  asm volatile("mma.sync.aligned.m16n8k16.row.col.f32.bf16.bf16.f32 "
    "{%0,%1,%2,%3}, {%4,%5,%6,%7}, {%8,%9}, {%0,%1,%2,%3};"
    : "+f"(d[0]),"+f"(d[1]),"+f"(d[2]),"+f"(d[3])
    : "r"(a[0]),"r"(a[1]),"r"(a[2]),"r"(a[3]),"r"(b0),"r"(b1));
}
__device__ __forceinline__ float tf32_rna(float x){
  uint32_t r;
  asm("cvt.rna.tf32.f32 %0, %1;" : "=r"(r) : "f"(x));
  return __uint_as_float(r);
}
__device__ __forceinline__ float gelu_exact(float x){
  return 0.5f*x*(1.f+erff(x*0.70710678118654752f));
}
__device__ __forceinline__ float softplusf(float x){
  return (x > 20.f) ? x : log1pf(expf(x));
}

#define MBAR_INIT(mb, c)  asm volatile("mbarrier.init.shared.b64 [%0], %1;" :: "r"(mb), "r"((uint32_t)(c)) : "memory")
#define MBAR_EXPECT_TX(mb, tx) asm volatile("mbarrier.arrive.expect_tx.shared.b64 _, [%0], %1;" :: "r"(mb), "r"((uint32_t)(tx)) : "memory")
#define MBAR_WAIT(mb, par) do {                                                   \
  uint32_t _m = (mb); uint32_t _p = (par); uint32_t _d;                           \
  asm volatile("{\n\t.reg .pred p;\n\t"                                           \
    "mbarrier.try_wait.parity.acquire.cta.shared::cta.b64 p, [%1], %2;\n\t"       \
    "selp.b32 %0, 1, 0, p;\n\t}" : "=r"(_d) : "r"(_m), "r"(_p) : "memory");       \
  if (!_d) {                                                                      \
    asm volatile("{\n\t.reg .pred P1;\n\t"                                        \
      "W_%=:\n\t"                                                                 \
      "mbarrier.try_wait.parity.acquire.cta.shared::cta.b64 P1, [%0], %1, 0x989680;\n\t" \
      "@P1 bra.uni D_%=;\n\t"                                                     \
      "bra.uni W_%=;\n\t"                                                         \
      "D_%=:\n\t}" :: "r"(_m), "r"(_p) : "memory");                               \
  }                                                                               \
} while(0)

__device__ __forceinline__ void bulk_g2s(uint32_t dst, const void* src, uint32_t bytes, uint32_t mbar){
  asm volatile("cp.async.bulk.shared::cluster.global.mbarrier::complete_tx::bytes [%0], [%1], %2, [%3];"
    :: "r"(dst), "l"(src), "r"(bytes), "r"(mbar) : "memory");
}

// ---------------- weight prep: tf32 round + chunk-tiled swizzled layout ----------------
__global__ void k_wprep(const float* __restrict__ w){
  int i = blockIdx.x*256 + threadIdx.x;
  int layer = i >> 14;
  int j = i & 16383;
  int o = j >> 6;
  int cu = j & 63;
  int chunk = cu >> 3, uu = cu & 7;
  const float* src = w + (size_t)layer*65536 + o*256 + cu*4;
  float4 v = *(const float4*)src;
  v.x = tf32_rna(v.x); v.y = tf32_rna(v.y); v.z = tf32_rna(v.z); v.w = tf32_rna(v.w);
  float* dst = g_wt + (size_t)layer*65536 + chunk*8192 + o*32 + ((uu ^ (o & 7)) << 2);
  *(float4*)dst = v;
}

// store 8 channels (c = lid*8) of position n into swizzled g_y
__device__ __forceinline__ void store_y(int n, int c, const float* o_){
  int nblk = n >> 6, row = n & 63;
  int cu0 = c >> 2;
  int chunk = cu0 >> 3, uu = cu0 & 7;
  float* base = g_y + (size_t)nblk*16384 + chunk*2048 + row*32;
  int r7 = row & 7;
  *(float4*)(base + ((uu ^ r7) << 2))       = *(const float4*)&o_[0];
  *(float4*)(base + (((uu+1) ^ r7) << 2))   = *(const float4*)&o_[4];
}

// ======= layer 1-3 dwln: 4 positions per warp, vectorized param loads =======
__global__ void __launch_bounds__(256) k_dwln(const float* __restrict__ mask,
                       const float* __restrict__ sw, const float* __restrict__ sb,
                       const float* __restrict__ gm, const float* __restrict__ bt, int dil){
  int w = threadIdx.x >> 5, lid = threadIdx.x & 31;
  int n0 = blockIdx.x*32 + w*4;
  int c = lid*8;

  float s3[24], sbv[8], gmv[8], btv[8];
  #pragma unroll
  for (int q=0;q<6;q++) *(float4*)&s3[q*4] = *(const float4*)&sw[c*3 + q*4];
  *(float4*)&sbv[0] = *(const float4*)&sb[c]; *(float4*)&sbv[4] = *(const float4*)&sb[c+4];
  *(float4*)&gmv[0] = *(const float4*)&gm[c]; *(float4*)&gmv[4] = *(const float4*)&gm[c+4];
  *(float4*)&btv[0] = *(const float4*)&bt[c]; *(float4*)&btv[4] = *(const float4*)&bt[c+4];

  float v[4][8];
  #pragma unroll
  for (int p=0;p<4;p++){
    int n = n0 + p;
    int t = n & (TLEN-1);
    float m0 = mask[n];
    float hc[8];
    *(float4*)&hc[0] = *(const float4*)&g_h[(size_t)n*HCH + c];
    *(float4*)&hc[4] = *(const float4*)&g_h[(size_t)n*HCH + c + 4];
    #pragma unroll
    for (int j=0;j<8;j++) v[p][j] = sbv[j] + s3[j*3+1]*hc[j]*m0;
    if (t >= dil){
      float mm = mask[n-dil];
      float hl[8];
      *(float4*)&hl[0] = *(const float4*)&g_h[(size_t)(n-dil)*HCH + c];
      *(float4*)&hl[4] = *(const float4*)&g_h[(size_t)(n-dil)*HCH + c + 4];
      #pragma unroll
      for (int j=0;j<8;j++) v[p][j] += s3[j*3+0]*hl[j]*mm;
    }
    if (t + dil < TLEN){
      float mm = mask[n+dil];
      float hr[8];
      *(float4*)&hr[0] = *(const float4*)&g_h[(size_t)(n+dil)*HCH + c];
      *(float4*)&hr[4] = *(const float4*)&g_h[(size_t)(n+dil)*HCH + c + 4];
      #pragma unroll
      for (int j=0;j<8;j++) v[p][j] += s3[j*3+2]*hr[j]*mm;
    }
  }

  #pragma unroll
  for (int p=0;p<4;p++){
    int n = n0 + p;
    float ls = 0.f;
    #pragma unroll
    for (int j=0;j<8;j++) ls += v[p][j];
    #pragma unroll
    for (int o=16;o;o>>=1) ls += __shfl_xor_sync(0xffffffffu, ls, o);
    float mean = ls * (1.f/HCH);
    float sq = 0.f;
    #pragma unroll
    for (int j=0;j<8;j++){ v[p][j] -= mean; sq += v[p][j]*v[p][j]; }
    #pragma unroll
    for (int o=16;o;o>>=1) sq += __shfl_xor_sync(0xffffffffu, sq, o);
    float rstd = rsqrtf(sq * (1.f/HCH) + 1e-5f);

    float o_[8];
    #pragma unroll
    for (int j=0;j<8;j++){
      float yn = v[p][j]*rstd*gmv[j] + btv[j];
      o_[j] = tf32_rna(gelu_exact(yn));
    }
    store_y(n, c, o_);
  }
}

// ======= layer-0 fused: pre-1x1 on the fly + dwconv(dil=1) + LN + GELU =======
__global__ void __launch_bounds__(256) k_dwln_pre(const float* __restrict__ x,
                           const float* __restrict__ mask,
                           const float* __restrict__ pw, const float* __restrict__ pb,
                           const float* __restrict__ sw, const float* __restrict__ sb,
                           const float* __restrict__ gm, const float* __restrict__ bt){
  int w = threadIdx.x >> 5, lid = threadIdx.x & 31;
  int n0 = blockIdx.x*32 + w*4;
  int t0 = n0 & (TLEN-1);
  int b = n0 >> 12;
  int c = lid*8;

  float pwv[16], pbv[8], s3[24], sbv[8], gmv[8], btv[8];
  #pragma unroll
  for (int q=0;q<4;q++) *(float4*)&pwv[q*4] = *(const float4*)&pw[c*2 + q*4];
  *(float4*)&pbv[0] = *(const float4*)&pb[c]; *(float4*)&pbv[4] = *(const float4*)&pb[c+4];
  #pragma unroll
  for (int q=0;q<6;q++) *(float4*)&s3[q*4] = *(const float4*)&sw[c*3 + q*4];
  *(float4*)&sbv[0] = *(const float4*)&sb[c]; *(float4*)&sbv[4] = *(const float4*)&sb[c+4];
  *(float4*)&gmv[0] = *(const float4*)&gm[c]; *(float4*)&gmv[4] = *(const float4*)&gm[c+4];
  *(float4*)&btv[0] = *(const float4*)&bt[c]; *(float4*)&btv[4] = *(const float4*)&bt[c+4];

  float x0v[6], x1v[6], mv[6];
  #pragma unroll
  for (int i=0;i<6;i++){
    int ti = t0 - 1 + i;
    bool ok = (ti >= 0) && (ti < TLEN);
    int tc = ok ? ti : 0;
    x0v[i] = x[(b*4+0)*TLEN + tc];
    x1v[i] = x[(b*4+1)*TLEN + tc];
    mv[i]  = ok ? mask[b*TLEN + tc] : 0.f;
  }

  float v[4][8];
  #pragma unroll
  for (int p=0;p<4;p++){
    int n = n0 + p;
    int t = t0 + p;
    bool hasL = (t >= 1), hasR = (t + 1 < TLEN);
    float hc[8];
    #pragma unroll
    for (int j=0;j<8;j++){
      float wa = pwv[j*2], wb = pwv[j*2+1], pbc = pbv[j];
      float h0 = fmaf(wa, x0v[p+1], fmaf(wb, x1v[p+1], pbc));
      hc[j] = h0;
      float acc = sbv[j] + s3[j*3+1]*h0*mv[p+1];
      if (hasL){ float hl = fmaf(wa, x0v[p],   fmaf(wb, x1v[p],   pbc)); acc += s3[j*3+0]*hl*mv[p]; }
      if (hasR){ float hr = fmaf(wa, x0v[p+2], fmaf(wb, x1v[p+2], pbc)); acc += s3[j*3+2]*hr*mv[p+2]; }
      v[p][j] = acc;
    }
    *(float4*)&g_h[(size_t)n*HCH + c]     = *(float4*)&hc[0];
    *(float4*)&g_h[(size_t)n*HCH + c + 4] = *(float4*)&hc[4];
  }

  #pragma unroll
  for (int p=0;p<4;p++){
    int n = n0 + p;
    float ls = 0.f;
    #pragma unroll
    for (int j=0;j<8;j++) ls += v[p][j];
    #pragma unroll
    for (int o=16;o;o>>=1) ls += __shfl_xor_sync(0xffffffffu, ls, o);
    float mean = ls * (1.f/HCH);
    float sq = 0.f;
    #pragma unroll
    for (int j=0;j<8;j++){ v[p][j] -= mean; sq += v[p][j]*v[p][j]; }
    #pragma unroll
    for (int o=16;o;o>>=1) sq += __shfl_xor_sync(0xffffffffu, sq, o);
    float rstd = rsqrtf(sq * (1.f/HCH) + 1e-5f);

    float o_[8];
    #pragma unroll
    for (int j=0;j<8;j++){
      float yn = v[p][j]*rstd*gmv[j] + btv[j];
      o_[j] = tf32_rna(gelu_exact(yn));
    }
    store_y(n, c, o_);
  }
}

// ======== fused tf32 mma GEMM, bulk async (R10 proven config) ========
// CTA: 64 positions x 256 out-ch, 256 threads, 8 warps (2M x 4N), warp tile 32x64.
#define OFF_A   0                 // 2 stages * 8192
#define OFF_B   16384             // 2 stages * 32768
#define OFF_PAR 81920             // 3 * 1024
#define OFF_RED 84992             // 64 rows * 8 floats = 2048
#define OFF_MBR 87040             // 2 mbarriers * 16B
#define GSMEM   87104

__global__ void __launch_bounds__(256, 2) k_gemmfused(int layer,
                       const float* __restrict__ bias,
                       const float* __restrict__ gm, const float* __restrict__ bt){
  extern __shared__ char smem[];
  uint32_t sbase = smem_u32(smem);
  float* s_bias = (float*)(smem + OFF_PAR);
  float* s_g    = (float*)(smem + OFF_PAR + 1024);
  float* s_bt   = (float*)(smem + OFF_PAR + 2048);
  float* s_red  = (float*)(smem + OFF_RED);

  int tid = threadIdx.x, lane = tid & 31, wid = tid >> 5;
  int warpM = wid >> 2, warpN = wid & 3;
  int g = lane >> 2, tig = lane & 3;
  int mat = lane >> 3, mr = lane & 7;
  int n0 = blockIdx.x * 64;

  const char* gB = (const char*)(g_wt + (size_t)layer*65536);
  const char* gA = (const char*)(g_y  + (size_t)blockIdx.x*16384);

  s_bias[tid] = bias[tid]; s_g[tid] = gm[tid]; s_bt[tid] = bt[tid];
  if (tid == 0){ MBAR_INIT(sbase + OFF_MBR, 1); MBAR_INIT(sbase + OFF_MBR + 16, 1); }
  __syncthreads();

  float acc[2][8][4];
  #pragma unroll
  for (int mf=0;mf<2;mf++)
    #pragma unroll
    for (int nf=0;nf<8;nf++)
      #pragma unroll
      for (int k=0;k<4;k++) acc[mf][nf][k]=0.f;

  int arow_l = (mat & 1)*8 + mr;   int amh = mat >> 1;
  int brow_l = (mat >> 1)*8 + mr;  int bmh = mat & 1;
  uint32_t aBase0 = sbase + OFF_A + (uint32_t)((warpM*32 + arow_l)*128);
  uint32_t bBase0 = sbase + OFF_B + (uint32_t)((warpN*64 + brow_l)*128);

  #define ISSUE(q) {                                                       \
    uint32_t _mb = sbase + OFF_MBR + ((q)&1)*16;                           \
    MBAR_EXPECT_TX(_mb, 40960);                                            \
    bulk_g2s(sbase + OFF_A + ((q)&1)*8192,  gA + (size_t)(q)*8192,  8192,  _mb); \
    bulk_g2s(sbase + OFF_B + ((q)&1)*32768, gB + (size_t)(q)*32768, 32768, _mb); \
  }

  if (tid == 0) ISSUE(0);

  for (int q = 0; q < 8; q++){
    if (tid == 0 && q + 1 < 8) ISSUE(q+1);
    MBAR_WAIT(sbase + OFF_MBR + (q&1)*16, (q>>1)&1);

    uint32_t aBase = aBase0 + (q&1)*8192;
    uint32_t bBase = bBase0 + (q&1)*32768;

    #pragma unroll
    for (int ks=0; ks<4; ks++){
      uint32_t swa = (uint32_t)(((2*ks + amh) ^ mr) << 4);
      uint32_t swb = (uint32_t)(((2*ks + bmh) ^ mr) << 4);
      unsigned afr[2][4];
      ldsm4(afr[0][0], afr[0][1], afr[0][2], afr[0][3], aBase + swa);
      ldsm4(afr[1][0], afr[1][1], afr[1][2], afr[1][3], aBase + 2048 + swa);
      unsigned bfr[8][2];
      #pragma unroll
      for (int np=0; np<4; np++){
        unsigned t0,t1,t2,t3;
        ldsm4(t0,t1,t2,t3, bBase + np*2048 + swb);
        bfr[2*np][0]=t0; bfr[2*np][1]=t1; bfr[2*np+1][0]=t2; bfr[2*np+1][1]=t3;
      }
      #pragma unroll
      for (int nf=0; nf<8; nf++){
        mma_tf32(acc[0][nf], afr[0], bfr[nf][0], bfr[nf][1]);
        mma_tf32(acc[1][nf], afr[1], bfr[nf][0], bfr[nf][1]);
      }
    }
    __syncthreads();
  }

  // ---- epilogue: bias, row stats, LN, GELU, residual ----
  float s[4]  = {0.f,0.f,0.f,0.f};
  float sq[4] = {0.f,0.f,0.f,0.f};
  #pragma unroll
  for (int mf=0; mf<2; mf++)
    #pragma unroll
    for (int nf=0; nf<8; nf++){
      int ch0 = warpN*64 + nf*8 + tig*2;
      float b0 = s_bias[ch0], b1 = s_bias[ch0+1];
      acc[mf][nf][0]+=b0; acc[mf][nf][1]+=b1;
      acc[mf][nf][2]+=b0; acc[mf][nf][3]+=b1;
      s [mf*2+0] += acc[mf][nf][0]+acc[mf][nf][1];
      sq[mf*2+0] += acc[mf][nf][0]*acc[mf][nf][0] + acc[mf][nf][1]*acc[mf][nf][1];
      s [mf*2+1] += acc[mf][nf][2]+acc[mf][nf][3];
      sq[mf*2+1] += acc[mf][nf][2]*acc[mf][nf][2] + acc[mf][nf][3]*acc[mf][nf][3];
    }
  #pragma unroll
  for (int sl=0; sl<4; sl++){
    s [sl] += __shfl_xor_sync(0xffffffffu, s [sl], 1);
    s [sl] += __shfl_xor_sync(0xffffffffu, s [sl], 2);
    sq[sl] += __shfl_xor_sync(0xffffffffu, sq[sl], 1);
    sq[sl] += __shfl_xor_sync(0xffffffffu, sq[sl], 2);
  }
  __syncthreads();
  if (tig == 0){
    #pragma unroll
    for (int sl=0; sl<4; sl++){
      int mf = sl >> 1, h = sl & 1;
      int row = warpM*32 + mf*16 + h*8 + g;
      s_red[row*8 + warpN*2 + 0] = s[sl];
      s_red[row*8 + warpN*2 + 1] = sq[sl];
    }
  }
  __syncthreads();

  float mean_[4], rstd_[4];
  #pragma unroll
  for (int sl=0; sl<4; sl++){
    int mf = sl >> 1, h = sl & 1;
    int row = warpM*32 + mf*16 + h*8 + g;
    float su = s_red[row*8+0]+s_red[row*8+2]+s_red[row*8+4]+s_red[row*8+6];
    float qq = s_red[row*8+1]+s_red[row*8+3]+s_red[row*8+5]+s_red[row*8+7];
    float mn = su * (1.f/HCH);
    float var = qq * (1.f/HCH) - mn*mn;
    mean_[sl] = mn;
    rstd_[sl] = rsqrtf(var + 1e-5f);
  }

  #pragma unroll
  for (int mf=0; mf<2; mf++)
    #pragma unroll
    for (int nf=0; nf<8; nf++){
      int ch0 = warpN*64 + nf*8 + tig*2;
      float g0 = s_g[ch0], g1 = s_g[ch0+1];
      float t0 = s_bt[ch0], t1 = s_bt[ch0+1];
      #pragma unroll
      for (int h=0; h<2; h++){
        int sl = mf*2 + h;
        int row = n0 + warpM*32 + mf*16 + h*8 + g;
        float v0 = (acc[mf][nf][h*2+0] - mean_[sl])*rstd_[sl]*g0 + t0;
        float v1 = (acc[mf][nf][h*2+1] - mean_[sl])*rstd_[sl]*g1 + t1;
        float2* ptr = (float2*)&g_h[(size_t)row*HCH + ch0];
        float2 hv = *ptr;
        hv.x += gelu_exact(v0);
        hv.y += gelu_exact(v1);
        *ptr = hv;
      }
    }
}

// ---------------- proj weight prep: bf16 hi/lo, chunked swizzled ----------------
// layout: [chunk(4)][row(64)][64 bf16], 16B unit uu stored at uu^(row&7)
__global__ void k_padw(const float* __restrict__ pjw, const float* __restrict__ pjb){
  int o = blockIdx.x, k = threadIdx.x;
  float w = (o < OUTCH) ? pjw[o*HCH + k] : 0.f;
  __nv_bfloat16 h = __float2bfloat16(w);
  __nv_bfloat16 l = __float2bfloat16(w - __bfloat162float(h));
  int chunk = k >> 6;
  int kk = k & 63;
  int uu = kk >> 3, pos = kk & 7;
  int off = chunk*4096 + o*64 + ((uu ^ (o & 7)) << 3) + pos;
  g_pwh[off] = h;
  g_pwl[off] = l;
  if (k == 0) g_pb[o] = (o < OUTCH) ? pjb[o] : 0.f;
}

// ---------------- projection: bf16 hi/lo mma, g_p = (W(h*m)+b)*m ----------------
// CTA 64 positions x 64 out. 8 warps: warpM = wid&3 (16 rows), warpN = wid>>2 (32 ch).
__global__ void __launch_bounds__(256) k_projmma(const float* __restrict__ mask){
  __shared__ __nv_bfloat16 sAh[64*64], sAl[64*64], sBh[64*64], sBl[64*64];
  __shared__ float s_pb[64];
  int tid = threadIdx.x, lane = tid & 31, wid = tid >> 5;
  int warpM = wid & 3, warpN = wid >> 2;
  int g = lane >> 2, tig = lane & 3;
  int mat = lane >> 3, mr = lane & 7;
  int n0 = blockIdx.x * 64;
  if (tid < 64) s_pb[tid] = g_pb[tid];

  uint32_t sah = smem_u32(sAh), sal = smem_u32(sAl);
  uint32_t sbh = smem_u32(sBh), sbl = smem_u32(sBl);

  float acc[4][4];
  #pragma unroll
  for (int nf=0;nf<4;nf++)
    #pragma unroll
    for (int k=0;k<4;k++) acc[nf][k]=0.f;

  int arow_l = (mat & 1)*8 + mr;   int amh = mat >> 1;
  int brow_l = (mat >> 1)*8 + mr;  int bmh = mat & 1;
  uint32_t aOffW = (uint32_t)((warpM*16 + arow_l)*128);
  uint32_t bOffW = (uint32_t)((warpN*32 + brow_l)*128);

  int row = tid >> 2;                 // 0..63
  int kq  = (tid & 3) * 16;           // 16 k-elems per thread
  float m_row = mask[n0 + row];
  int r7 = row & 7;
  int u0 = (tid & 3) * 2;

  for (int chunk=0; chunk<4; chunk++){
    __syncthreads();
    // ---- A: h*mask -> bf16 hi/lo, swizzled ----
    {
      float hv[16];
      const float* src = &g_h[(size_t)(n0+row)*HCH + chunk*64 + kq];
      *(float4*)&hv[0]  = *(const float4*)&src[0];
      *(float4*)&hv[4]  = *(const float4*)&src[4];
      *(float4*)&hv[8]  = *(const float4*)&src[8];
      *(float4*)&hv[12] = *(const float4*)&src[12];
      __nv_bfloat16 hi[16], lo[16];
      #pragma unroll
      for (int j=0;j<16;j++){
        float v = hv[j]*m_row;
        __nv_bfloat16 h = __float2bfloat16(v);
        hi[j] = h;
        lo[j] = __float2bfloat16(v - __bfloat162float(h));
      }
      uint32_t o0 = (uint32_t)(row*128 + ((u0 ^ r7) << 4));
      uint32_t o1 = (uint32_t)(row*128 + (((u0+1) ^ r7) << 4));
      *(uint4*)((char*)sAh + o0) = *(uint4*)&hi[0];
      *(uint4*)((char*)sAh + o1) = *(uint4*)&hi[8];
      *(uint4*)((char*)sAl + o0) = *(uint4*)&lo[0];
      *(uint4*)((char*)sAl + o1) = *(uint4*)&lo[8];
    }
    // ---- B: copy pre-swizzled 8KB each ----
    {
      const uint4* srcH = (const uint4*)&g_pwh[chunk*4096];
      const uint4* srcL = (const uint4*)&g_pwl[chunk*4096];
      ((uint4*)sBh)[tid]       = srcH[tid];
      ((uint4*)sBh)[tid + 256] = srcH[tid + 256];
      ((uint4*)sBl)[tid]       = srcL[tid];
      ((uint4*)sBl)[tid + 256] = srcL[tid + 256];
    }
    __syncthreads();

    #pragma unroll
    for (int ks=0; ks<2; ks++){   // K=64 bf16 per chunk, 32 per mma k-step
      uint32_t swa = (uint32_t)(((2*(ks*2) + amh*2) ^ 0) << 0); // placeholder, computed below
      // k-step covers 32 bf16 = 64B = 4 units; ldsm x4 handles 16 bf16 (32B = 2 units)
      // -> two k16 substeps per ks: do k16 granularity directly:
      (void)swa;
      #pragma unroll
      for (int kh=0; kh<2; kh++){
        int kst = ks*2 + kh;     // k16 step 0..3
        uint32_t ua = (uint32_t)(((2*kst + amh) ^ mr) << 4);
        uint32_t ub = (uint32_t)(((2*kst + bmh) ^ mr) << 4);
        unsigned ah[4], al[4];
        ldsm4(ah[0],ah[1],ah[2],ah[3], sah + aOffW + ua);
        ldsm4(al[0],al[1],al[2],al[3], sal + aOffW + ua);
        unsigned bh[4][2], bl[4][2];
        #pragma unroll
        for (int np=0; np<2; np++){
          unsigned t0,t1,t2,t3;
          ldsm4(t0,t1,t2,t3, sbh + bOffW + np*2048 + ub);
          bh[2*np][0]=t0; bh[2*np][1]=t1; bh[2*np+1][0]=t2; bh[2*np+1][1]=t3;
          ldsm4(t0,t1,t2,t3, sbl + bOffW + np*2048 + ub);
          bl[2*np][0]=t0; bl[2*np][1]=t1; bl[2*np+1][0]=t2; bl[2*np+1][1]=t3;
        }
        #pragma unroll
        for (int nf=0; nf<4; nf++){
          mma_bf16(acc[nf], ah, bh[nf][0], bh[nf][1]);
          mma_bf16(acc[nf], ah, bl[nf][0], bl[nf][1]);
          mma_bf16(acc[nf], al, bh[nf][0], bh[nf][1]);
        }
      }
    }
  }

  // ---- epilogue: +bias, *mask, write g_p ----
  #pragma unroll
  for (int nf=0; nf<4; nf++){
    int ch0 = warpN*32 + nf*8 + tig*2;
    float b0 = s_pb[ch0], b1 = s_pb[ch0+1];
    #pragma unroll
    for (int h=0; h<2; h++){
      int r = n0 + warpM*16 + h*8 + g;
      float m = mask[r];
      float2 v;
      v.x = (acc[nf][h*2+0] + b0) * m;
      v.y = (acc[nf][h*2+1] + b1) * m;
      *(float2*)&g_p[(size_t)r*OPAD + ch0] = v;
    }
  }
}

// ---------------- rational-quadratic spline ----------------
__global__ void k_spline(const float* __restrict__ x, const float* __restrict__ mask,
                         float* __restrict__ out){
  int i = blockIdx.x*256 + threadIdx.x;
  int t = i & (TLEN-1);
  int bc = i >> 12;
  int c = bc & 1, b = bc >> 1;
  float m = mask[b*TLEN + t];
  const float* p = &g_p[(size_t)(b*TLEN + t)*OPAD + c*29];
  float x1 = x[(b*4 + 2 + c)*TLEN + t];

  out[(b*4 + c)*TLEN + t] = x[(b*4 + c)*TLEN + t] * m;

  const float scale = 0.0625f;
  float ew[10], eh[10];
  float mw = -1e30f, mh = -1e30f;
  #pragma unroll
  for (int j=0;j<10;j++){ mw = fmaxf(mw, p[j]*scale); mh = fmaxf(mh, p[10+j]*scale); }
  float sw = 0.f, sh = 0.f;
  #pragma unroll
  for (int j=0;j<10;j++){
    ew[j] = expf(p[j]*scale - mw);    sw += ew[j];
    eh[j] = expf(p[10+j]*scale - mh); sh += eh[j];
  }
  float invsw = 1.f/sw, invsh = 1.f/sh;
  float xc = fminf(fmaxf(x1, -5.f), 5.f);

  float cumw = 0.f, cumh = 0.f;
  float cwj = -5.f, chj = -5.f;
  int idx = 9;
  float in_cw = 0.f, in_w = 1.f, in_ch = 0.f, in_h = 1.f;
  bool found = false;
  #pragma unroll
  for (int j=0;j<10;j++){
    cumw += 0.001f + 0.99f*ew[j]*invsw;
    cumh += 0.001f + 0.99f*eh[j]*invsh;
    float nw = (j==9) ? 5.f : fmaf(10.f, cumw, -5.f);
    float nh = (j==9) ? 5.f : fmaf(10.f, cumh, -5.f);
    if (!found && (xc < nw || j==9)){
      found = true; idx = j;
      in_cw = cwj; in_w = nw - cwj;
      in_ch = chj; in_h = nh - chj;
    }
    cwj = nw; chj = nh;
  }
  float dk  = (idx==0) ? 1.f : 0.001f + softplusf(p[20 + idx - 1]);
  float dk1 = (idx==9) ? 1.f : 0.001f + softplusf(p[20 + idx]);
  float delta = in_h / in_w;
  float th  = (xc - in_cw) / in_w;
  float th2 = th*th;
  float t1m = th*(1.f - th);
  float num = in_h * (delta*th2 + dk*t1m);
  float den = delta + (dk + dk1 - 2.f*delta)*t1m;
  float y = in_ch + num/den;
  float omt = 1.f - th;
  float dnum = delta*delta*(dk1*th2 + 2.f*delta*t1m + dk*omt*omt);
  float lad = logf(dnum) - 2.f*logf(den);

  bool inside = (x1 >= -5.f) && (x1 <= 5.f);
  y   = inside ? y   : x1;
  lad = inside ? lad : 0.f;

  out[(b*4 + 2 + c)*TLEN + t] = y * m;
  g_lad[i] = lad * m;
}

__global__ void k_reduce(float* __restrict__ out){
  int b = blockIdx.x;
  float s = 0.f;
  for (int j = threadIdx.x; j < 2*TLEN; j += 256) s += g_lad[b*2*TLEN + j];
  __shared__ float sm[8];
  #pragma unroll
  for (int o=16;o;o>>=1) s += __shfl_xor_sync(0xffffffffu, s, o);
  if ((threadIdx.x&31)==0) sm[threadIdx.x>>5]=s;
  __syncthreads();
  if (threadIdx.x == 0){
    float r = sm[0]+sm[1]+sm[2]+sm[3]+sm[4]+sm[5]+sm[6]+sm[7];
    out[BATCH*4*TLEN + b] = r;
  }
}

extern "C" void kernel_launch(void* const* d_in, const int* in_sizes, int n_in,
                              void* d_out, int out_size){
  const float* x     = (const float*)d_in[0];
  const float* xm    = (const float*)d_in[1];
  const float* pre_w = (const float*)d_in[2];
  const float* pre_b = (const float*)d_in[3];
  const float* sep_w = (const float*)d_in[4];
  const float* sep_b = (const float*)d_in[5];
  const float* c1w   = (const float*)d_in[6];
  const float* c1b   = (const float*)d_in[7];
  const float* n1g   = (const float*)d_in[8];
  const float* n1b   = (const float*)d_in[9];
  const float* n2g   = (const float*)d_in[10];
  const float* n2b   = (const float*)d_in[11];
  const float* pjw   = (const float*)d_in[12];
  const float* pjb   = (const float*)d_in[13];
  float* out = (float*)d_out;

  static int smem_set = 0;
  if (!smem_set){
    cudaFuncSetAttribute(k_gemmfused, cudaFuncAttributeMaxDynamicSharedMemorySize, GSMEM);
    smem_set = 1;
  }

  k_wprep<<<(LLAYER*HCH*HCH/4)/256, 256>>>(c1w);
  k_padw<<<OPAD, HCH>>>(pjw, pjb);

  int dil = 1;
  for (int i=0;i<LLAYER;i++){
    if (i == 0)
      k_dwln_pre<<<NPOS/32, 256>>>(x, xm, pre_w, pre_b, sep_w, sep_b, n1g, n1b);
    else
      k_dwln<<<NPOS/32, 256>>>(xm, sep_w + i*HCH*3, sep_b + i*HCH,
                               n1g + i*HCH, n1b + i*HCH, dil);
    k_gemmfused<<<NPOS/64, 256, GSMEM>>>(i, c1b + i*HCH, n2g + i*HCH, n2b + i*HCH);
    dil *= 3;
  }

  k_projmma<<<NPOS/64, 256>>>(xm);
  k_spline<<<(BATCH*2*TLEN)/256, 256>>>(x, xm, out);
  k_reduce<<<BATCH, 256>>>(out);
}